// round 16
// baseline (speedup 1.0000x reference)
#include <cuda_runtime.h>
#include <cstdint>
#include <climits>

#define N_PTS   400000
#define NXY     468
#define CANVAS  (468 * 468)          // 219024
#define NB      ((CANVAS + 255) / 256)   // 856
#define TVOX    32
#define NVT     ((CANVAS + TVOX - 1) / TVOX)   // 6846 voxel tiles
#define VXY     0.32f
#define VZf     6.0f
#define PCMINX  (-74.88f)
#define PCMINY  (-74.88f)
#define PCMINZ  (-2.0f)

// -------- scratch (static device globals; no allocations allowed) ----------
__device__ int   g_flat[N_PTS];
__device__ int   g_cnt[CANVAS];
__device__ float g_vsum[CANVAS * 3];
__device__ int   g_bsum[NB];
__device__ int   g_boff[NB];
__device__ int   g_off[CANVAS + 1];
__device__ int   g_fill[CANVAS];
__device__ int   g_sorted[N_PTS];
__device__ int   g_sflat[N_PTS];

// total-order float<->int map (float max == int max on mapped values)
__device__ __forceinline__ int fmap_bits(float v) {
    int b = __float_as_int(v);
    return b >= 0 ? b : b ^ 0x7fffffff;
}
__device__ __forceinline__ float funmap_bits(int b) {
    return __int_as_float(b >= 0 ? b : b ^ 0x7fffffff);
}
// INT_MIN unmaps to NaN; fmaxf(NaN, 0) == 0 -> empty voxels exact.

// ---------------------------------------------------------------------------
// K0: zero cnt / vsum / fill
// ---------------------------------------------------------------------------
__global__ void k_zero() {
    int idx = blockIdx.x * blockDim.x + threadIdx.x;
    int stride = gridDim.x * blockDim.x;
    for (int i = idx; i < CANVAS; i += stride) {
        g_cnt[i] = 0;
        g_fill[i] = 0;
        g_vsum[3 * i + 0] = 0.f;
        g_vsum[3 * i + 1] = 0.f;
        g_vsum[3 * i + 2] = 0.f;
    }
}

// ---------------------------------------------------------------------------
// K1: per-point voxel index + count / xyz-sum scatter
// ---------------------------------------------------------------------------
__device__ __forceinline__ int voxel_coord(float v, float vmin, float vox, int nmax) {
    int c = (int)floorf(__fdiv_rn(v - vmin, vox));
    return min(max(c, 0), nmax - 1);
}

__global__ void k_scatter(const float* __restrict__ pts) {
    int i = blockIdx.x * blockDim.x + threadIdx.x;
    if (i >= N_PTS) return;
    float x = pts[i * 5 + 0];
    float y = pts[i * 5 + 1];
    float z = pts[i * 5 + 2];
    int cx = voxel_coord(x, PCMINX, VXY, NXY);
    int cy = voxel_coord(y, PCMINY, VXY, NXY);
    int flat = cy * NXY + cx;          // NZ==1 -> cz always 0
    g_flat[i] = flat;
    atomicAdd(&g_cnt[flat], 1);
    atomicAdd(&g_vsum[3 * flat + 0], x);
    atomicAdd(&g_vsum[3 * flat + 1], y);
    atomicAdd(&g_vsum[3 * flat + 2], z);
}

// ---------------------------------------------------------------------------
// Counting-sort scaffolding: 2-level exclusive prefix sum over g_cnt
// ---------------------------------------------------------------------------
__global__ void k_scan1() {
    __shared__ int s[256];
    int t = threadIdx.x, b = blockIdx.x, i = b * 256 + t;
    s[t] = (i < CANVAS) ? g_cnt[i] : 0;
    __syncthreads();
    for (int d = 128; d > 0; d >>= 1) {
        if (t < d) s[t] += s[t + d];
        __syncthreads();
    }
    if (t == 0) g_bsum[b] = s[0];
}

__global__ void k_scan2() {
    __shared__ int s[1024];
    int t = threadIdx.x;
    int v = (t < NB) ? g_bsum[t] : 0;
    s[t] = v;
    __syncthreads();
    for (int d = 1; d < 1024; d <<= 1) {
        int x = (t >= d) ? s[t - d] : 0;
        __syncthreads();
        s[t] += x;
        __syncthreads();
    }
    if (t < NB) g_boff[t] = s[t] - v;     // exclusive
    if (t == 0) g_off[CANVAS] = N_PTS;
}

__global__ void k_scan3() {
    __shared__ int s[256];
    int t = threadIdx.x, b = blockIdx.x, i = b * 256 + t;
    int v = (i < CANVAS) ? g_cnt[i] : 0;
    s[t] = v;
    __syncthreads();
    for (int d = 1; d < 256; d <<= 1) {
        int x = (t >= d) ? s[t - d] : 0;
        __syncthreads();
        s[t] += x;
        __syncthreads();
    }
    if (i < CANVAS) g_off[i] = g_boff[b] + s[t] - v;
}

__global__ void k_fill() {
    int i = blockIdx.x * blockDim.x + threadIdx.x;
    if (i >= N_PTS) return;
    int flat = g_flat[i];
    int pos = g_off[flat] + atomicAdd(&g_fill[flat], 1);
    g_sorted[pos] = i;
    g_sflat[pos] = flat;
}

// ---------------------------------------------------------------------------
// K_MAIN: one block per 32-voxel tile; fully fused, smem-only maxes.
// smem word layout (total 14242 words = 56968 B -> 4 blocks/SM):
//   sW1   [0,704)        W1
//   sWX   [704,4800)     W2 chunk (rows 0..63 in point loop; 64..127 after)
//   sA    [4800,9152)    64x68 pf1 tile (point chunk)
//   sV1   [9152,11264)   32x66 int  (pf1 segment max, init 0)
//   sM    [11264,13312)  32x64 int  (mapped pre-relu max, init INT_MIN)
//   sVox  [13312,13472)  32x5 voxel stats
//   sF    [13472,14176)  64x11 point features
//   sLV   [14176,14240)  local voxel per point slot
//   sScal [14240,14242)  p_start, p_end
// ---------------------------------------------------------------------------
#define SA_LD 68
#define SV_LD 66
#define SMEM_MAIN_WORDS 14242
#define SMEM_MAIN_BYTES (SMEM_MAIN_WORDS * 4)   // 56968

__global__ __launch_bounds__(256)
void k_main(const float* __restrict__ pts, const float* __restrict__ W1,
            const float* __restrict__ W2, float* __restrict__ out) {
    extern __shared__ int smem_i[];
    float* smem_f = (float*)smem_i;
    float* sW1  = smem_f;
    float* sWX  = smem_f + 704;
    float* sA   = smem_f + 4800;
    int*   sV1  = smem_i + 9152;
    int*   sM   = smem_i + 11264;
    float* sVox = smem_f + 13312;
    float* sF   = smem_f + 13472;
    int*   sLV  = smem_i + 14176;
    int*   sScal = smem_i + 14240;

    int tid = threadIdx.x;
    int v0 = blockIdx.x * TVOX;
    int tx = tid & 15;
    int ty = tid >> 4;

    for (int i = tid; i < 704; i += 256) sW1[i] = W1[i];
    for (int i = tid; i < 4096; i += 256) sWX[i] = W2[i];          // rows 0..63
    for (int i = tid; i < TVOX * SV_LD; i += 256) sV1[i] = 0;
    for (int i = tid; i < TVOX * 64; i += 256) sM[i] = INT_MIN;

    // per-voxel stats (once per tile)
    if (tid < TVOX) {
        int v = v0 + tid;
        float mx = 0.f, my = 0.f, mz = 0.f, cenx = 0.f, ceny = 0.f;
        if (v < CANVAS) {
            float inv = 1.0f / fmaxf((float)g_cnt[v], 1.0f);
            mx = g_vsum[3 * v + 0] * inv;
            my = g_vsum[3 * v + 1] * inv;
            mz = g_vsum[3 * v + 2] * inv;
            int cxv = v % NXY;
            int cyv = v / NXY;
            cenx = (float)cxv * VXY + (VXY * 0.5f + PCMINX);
            ceny = (float)cyv * VXY + (VXY * 0.5f + PCMINY);
        }
        float* d = sVox + tid * 5;
        d[0] = mx; d[1] = my; d[2] = mz; d[3] = cenx; d[4] = ceny;
    }
    if (tid == 0) {
        sScal[0] = g_off[v0];
        sScal[1] = g_off[min(v0 + TVOX, CANVAS)];
    }
    __syncthreads();
    int p_start = sScal[0], p_end = sScal[1];

    // ---- point loop: 64-point chunks of this tile's sorted points
    for (int c0 = p_start; c0 < p_end; c0 += 64) {
        __syncthreads();   // previous chunk's GEMM/atomics done before overwrite

        // phase 0: one thread per point slot builds features
        if (tid < 64) {
            int pos = c0 + tid;
            int lv = -1;
            float* f = sF + tid * 11;
            if (pos < p_end) {
                int pi = g_sorted[pos];
                lv = g_sflat[pos] - v0;
                float x  = pts[pi * 5 + 0];
                float y  = pts[pi * 5 + 1];
                float z  = pts[pi * 5 + 2];
                float p3 = pts[pi * 5 + 3];
                float p4 = pts[pi * 5 + 4];
                const float* vx = sVox + lv * 5;
                f[0] = x;  f[1] = y;  f[2] = z;  f[3] = p3;  f[4] = p4;
                f[5] = x - vx[0];  f[6] = y - vx[1];  f[7] = z - vx[2];
                f[8] = x - vx[3];  f[9] = y - vx[4];
                f[10] = z - (VZf * 0.5f + PCMINZ);
            } else {
                #pragma unroll
                for (int k = 0; k < 11; k++) f[k] = 0.f;
            }
            sLV[tid] = lv;
        }
        __syncthreads();

        // phase 1: pf1 channels; thread = (pt, cg): channels cg*16..+15
        {
            int pt = tid >> 2;
            int cg = tid & 3;
            int lv = sLV[pt];

            float f[11];
            #pragma unroll
            for (int k = 0; k < 11; k++) f[k] = sF[pt * 11 + k];

            const float4* w4 = (const float4*)sW1;   // [11][16] float4
            #pragma unroll
            for (int c4 = 0; c4 < 4; c4++) {
                int ch = cg * 16 + c4 * 4;
                float a0 = 0.f, a1 = 0.f, a2 = 0.f, a3 = 0.f;
                #pragma unroll
                for (int k = 0; k < 11; k++) {
                    float4 w = w4[k * 16 + (ch >> 2)];
                    a0 = fmaf(f[k], w.x, a0);
                    a1 = fmaf(f[k], w.y, a1);
                    a2 = fmaf(f[k], w.z, a2);
                    a3 = fmaf(f[k], w.w, a3);
                }
                a0 = fmaxf(a0, 0.f); a1 = fmaxf(a1, 0.f);
                a2 = fmaxf(a2, 0.f); a3 = fmaxf(a3, 0.f);

                float* d = sA + pt * SA_LD + ch;
                d[0] = a0; d[1] = a1; d[2] = a2; d[3] = a3;

                if (lv >= 0) {     // smem segment max (relu>=0, init 0 -> exact)
                    int* vb = &sV1[lv * SV_LD + ch];
                    if (a0 > 0.f) atomicMax(vb + 0, __float_as_int(a0));
                    if (a1 > 0.f) atomicMax(vb + 1, __float_as_int(a1));
                    if (a2 > 0.f) atomicMax(vb + 2, __float_as_int(a2));
                    if (a3 > 0.f) atomicMax(vb + 3, __float_as_int(a3));
                }
            }
        }
        __syncthreads();

        // phase 2: GEMM s = sA @ W2a (4x4 micro-tile, K=64)
        float acc[4][4];
        #pragma unroll
        for (int r = 0; r < 4; r++)
            #pragma unroll
            for (int c = 0; c < 4; c++) acc[r][c] = 0.f;

        #pragma unroll 16
        for (int k = 0; k < 64; k++) {
            float4 b = *(const float4*)&sWX[k * 64 + tx * 4];
            float a0 = sA[(ty * 4 + 0) * SA_LD + k];
            float a1 = sA[(ty * 4 + 1) * SA_LD + k];
            float a2 = sA[(ty * 4 + 2) * SA_LD + k];
            float a3 = sA[(ty * 4 + 3) * SA_LD + k];
            acc[0][0] = fmaf(a0, b.x, acc[0][0]); acc[0][1] = fmaf(a0, b.y, acc[0][1]);
            acc[0][2] = fmaf(a0, b.z, acc[0][2]); acc[0][3] = fmaf(a0, b.w, acc[0][3]);
            acc[1][0] = fmaf(a1, b.x, acc[1][0]); acc[1][1] = fmaf(a1, b.y, acc[1][1]);
            acc[1][2] = fmaf(a1, b.z, acc[1][2]); acc[1][3] = fmaf(a1, b.w, acc[1][3]);
            acc[2][0] = fmaf(a2, b.x, acc[2][0]); acc[2][1] = fmaf(a2, b.y, acc[2][1]);
            acc[2][2] = fmaf(a2, b.z, acc[2][2]); acc[2][3] = fmaf(a2, b.w, acc[2][3]);
            acc[3][0] = fmaf(a3, b.x, acc[3][0]); acc[3][1] = fmaf(a3, b.y, acc[3][1]);
            acc[3][2] = fmaf(a3, b.z, acc[3][2]); acc[3][3] = fmaf(a3, b.w, acc[3][3]);
        }

        // pre-relu segment max into sM (mapped, smem)
        #pragma unroll
        for (int r = 0; r < 4; r++) {
            int lv = sLV[ty * 4 + r];
            if (lv >= 0) {
                int* o = &sM[lv * 64 + tx * 4];
                #pragma unroll
                for (int c = 0; c < 4; c++)
                    atomicMax(o + c, fmap_bits(acc[r][c]));
            }
        }
    }
    __syncthreads();

    // ---- final voxel GEMM: B = W2 rows 64..127, 32 rows -> 2x4 micro-tile
    for (int i = tid; i < 4096; i += 256) sWX[i] = W2[4096 + i];
    __syncthreads();

    float acc[2][4];
    #pragma unroll
    for (int r = 0; r < 2; r++)
        #pragma unroll
        for (int c = 0; c < 4; c++) acc[r][c] = 0.f;

    #pragma unroll 16
    for (int k = 0; k < 64; k++) {
        float4 b = *(const float4*)&sWX[k * 64 + tx * 4];
        float a0 = __int_as_float(sV1[(ty * 2 + 0) * SV_LD + k]);
        float a1 = __int_as_float(sV1[(ty * 2 + 1) * SV_LD + k]);
        acc[0][0] = fmaf(a0, b.x, acc[0][0]); acc[0][1] = fmaf(a0, b.y, acc[0][1]);
        acc[0][2] = fmaf(a0, b.z, acc[0][2]); acc[0][3] = fmaf(a0, b.w, acc[0][3]);
        acc[1][0] = fmaf(a1, b.x, acc[1][0]); acc[1][1] = fmaf(a1, b.y, acc[1][1]);
        acc[1][2] = fmaf(a1, b.z, acc[1][2]); acc[1][3] = fmaf(a1, b.w, acc[1][3]);
    }

    // dense epilogue: out = relu(acc + unmap(sM))
    #pragma unroll
    for (int r = 0; r < 2; r++) {
        int lrow = ty * 2 + r;
        int v = v0 + lrow;
        if (v >= CANVAS) continue;
        const int* mrow = &sM[lrow * 64 + tx * 4];
        float4 o;
        o.x = fmaxf(acc[r][0] + funmap_bits(mrow[0]), 0.f);
        o.y = fmaxf(acc[r][1] + funmap_bits(mrow[1]), 0.f);
        o.z = fmaxf(acc[r][2] + funmap_bits(mrow[2]), 0.f);
        o.w = fmaxf(acc[r][3] + funmap_bits(mrow[3]), 0.f);
        *(float4*)(out + (size_t)v * 64 + tx * 4) = o;
    }
}

// ---------------------------------------------------------------------------
extern "C" void kernel_launch(void* const* d_in, const int* in_sizes, int n_in,
                              void* d_out, int out_size) {
    const float* points = (const float*)d_in[0];  // [400000, 5]
    const float* W1     = (const float*)d_in[1];  // [11, 64]
    const float* W2     = (const float*)d_in[2];  // [128, 64]
    float* out = (float*)d_out;                   // [219024, 64]

    cudaFuncSetAttribute(k_main, cudaFuncAttributeMaxDynamicSharedMemorySize,
                         SMEM_MAIN_BYTES);

    k_zero<<<1024, 256>>>();
    k_scatter<<<(N_PTS + 255) / 256, 256>>>(points);
    k_scan1<<<NB, 256>>>();
    k_scan2<<<1, 1024>>>();
    k_scan3<<<NB, 256>>>();
    k_fill<<<(N_PTS + 255) / 256, 256>>>();
    k_main<<<NVT, 256, SMEM_MAIN_BYTES>>>(points, W1, W2, out);
}

// round 17
// speedup vs baseline: 1.1283x; 1.1283x over previous
#include <cuda_runtime.h>
#include <cstdint>
#include <climits>

#define N_PTS   400000
#define NXY     468
#define CANVAS  (468 * 468)          // 219024
#define NB      ((CANVAS + 255) / 256)   // 856
#define TVOX    64
#define NVT     ((CANVAS + TVOX - 1) / TVOX)   // 3423 voxel tiles
#define VXY     0.32f
#define VZf     6.0f
#define PCMINX  (-74.88f)
#define PCMINY  (-74.88f)
#define PCMINZ  (-2.0f)

// -------- scratch (static device globals; no allocations allowed) ----------
__device__ int   g_flat[N_PTS];
__device__ int   g_cnt[CANVAS];
__device__ float g_vsum[CANVAS * 3];
__device__ int   g_bsum[NB];
__device__ int   g_boff[NB];
__device__ int   g_off[CANVAS + 1];
__device__ int   g_fill[CANVAS];
__device__ int   g_sorted[N_PTS];
__device__ int   g_sflat[N_PTS];

// total-order float<->int map (float max == int max on mapped values)
__device__ __forceinline__ int fmap_bits(float v) {
    int b = __float_as_int(v);
    return b >= 0 ? b : b ^ 0x7fffffff;
}
__device__ __forceinline__ float funmap_bits(int b) {
    return __int_as_float(b >= 0 ? b : b ^ 0x7fffffff);
}
// INT_MIN unmaps to NaN; fmaxf(NaN, 0) == 0 -> empty voxels exact.

// ---------------------------------------------------------------------------
// K0: zero cnt / vsum / fill
// ---------------------------------------------------------------------------
__global__ void k_zero() {
    int idx = blockIdx.x * blockDim.x + threadIdx.x;
    int stride = gridDim.x * blockDim.x;
    for (int i = idx; i < CANVAS; i += stride) {
        g_cnt[i] = 0;
        g_fill[i] = 0;
        g_vsum[3 * i + 0] = 0.f;
        g_vsum[3 * i + 1] = 0.f;
        g_vsum[3 * i + 2] = 0.f;
    }
}

// ---------------------------------------------------------------------------
// K1: per-point voxel index + count / xyz-sum scatter
// ---------------------------------------------------------------------------
__device__ __forceinline__ int voxel_coord(float v, float vmin, float vox, int nmax) {
    int c = (int)floorf(__fdiv_rn(v - vmin, vox));
    return min(max(c, 0), nmax - 1);
}

__global__ void k_scatter(const float* __restrict__ pts) {
    int i = blockIdx.x * blockDim.x + threadIdx.x;
    if (i >= N_PTS) return;
    float x = pts[i * 5 + 0];
    float y = pts[i * 5 + 1];
    float z = pts[i * 5 + 2];
    int cx = voxel_coord(x, PCMINX, VXY, NXY);
    int cy = voxel_coord(y, PCMINY, VXY, NXY);
    int flat = cy * NXY + cx;          // NZ==1 -> cz always 0
    g_flat[i] = flat;
    atomicAdd(&g_cnt[flat], 1);
    atomicAdd(&g_vsum[3 * flat + 0], x);
    atomicAdd(&g_vsum[3 * flat + 1], y);
    atomicAdd(&g_vsum[3 * flat + 2], z);
}

// ---------------------------------------------------------------------------
// Counting-sort scaffolding: 2-level exclusive prefix sum over g_cnt
// ---------------------------------------------------------------------------
__global__ void k_scan1() {
    __shared__ int s[256];
    int t = threadIdx.x, b = blockIdx.x, i = b * 256 + t;
    s[t] = (i < CANVAS) ? g_cnt[i] : 0;
    __syncthreads();
    for (int d = 128; d > 0; d >>= 1) {
        if (t < d) s[t] += s[t + d];
        __syncthreads();
    }
    if (t == 0) g_bsum[b] = s[0];
}

__global__ void k_scan2() {
    __shared__ int s[1024];
    int t = threadIdx.x;
    int v = (t < NB) ? g_bsum[t] : 0;
    s[t] = v;
    __syncthreads();
    for (int d = 1; d < 1024; d <<= 1) {
        int x = (t >= d) ? s[t - d] : 0;
        __syncthreads();
        s[t] += x;
        __syncthreads();
    }
    if (t < NB) g_boff[t] = s[t] - v;     // exclusive
    if (t == 0) g_off[CANVAS] = N_PTS;
}

__global__ void k_scan3() {
    __shared__ int s[256];
    int t = threadIdx.x, b = blockIdx.x, i = b * 256 + t;
    int v = (i < CANVAS) ? g_cnt[i] : 0;
    s[t] = v;
    __syncthreads();
    for (int d = 1; d < 256; d <<= 1) {
        int x = (t >= d) ? s[t - d] : 0;
        __syncthreads();
        s[t] += x;
        __syncthreads();
    }
    if (i < CANVAS) g_off[i] = g_boff[b] + s[t] - v;
}

__global__ void k_fill() {
    int i = blockIdx.x * blockDim.x + threadIdx.x;
    if (i >= N_PTS) return;
    int flat = g_flat[i];
    int pos = g_off[flat] + atomicAdd(&g_fill[flat], 1);
    g_sorted[pos] = i;
    g_sflat[pos] = flat;
}

// ---------------------------------------------------------------------------
// K_MAIN (R15-proven + padded-row-group skip): one block per 64-voxel tile.
// smem word layout (18562 words = 74248 B -> 3 blocks/SM):
//   sW1   [0,704)       W1
//   sWX   [704,4800)    W2 chunk (rows 0..63 during point loop; 64..127 after)
//   sA    [4800,9152)   64x68 pf1 tile
//   sV1   [9152,13248)  64x64 int  (pf1 segment max, init 0)
//   sM    [13248,17344) 64x64 int  (mapped pre-relu max, init INT_MIN)
//   sVox  [17344,17728) 64x6 voxel stats
//   sF    [17728,18496) 64x12 point features
//   sLV   [18496,18560) local voxel per point slot
//   sScal [18560,18562) p_start, p_end
// ---------------------------------------------------------------------------
#define SA_LD 68
#define SMEM_MAIN_WORDS 18562
#define SMEM_MAIN_BYTES (SMEM_MAIN_WORDS * 4)   // 74248

__global__ __launch_bounds__(256)
void k_main(const float* __restrict__ pts, const float* __restrict__ W1,
            const float* __restrict__ W2, float* __restrict__ out) {
    extern __shared__ int smem_i[];
    float* smem_f = (float*)smem_i;
    float* sW1  = smem_f;
    float* sWX  = smem_f + 704;
    float* sA   = smem_f + 4800;
    int*   sV1  = smem_i + 9152;
    int*   sM   = smem_i + 13248;
    float* sVox = smem_f + 17344;
    float* sF   = smem_f + 17728;
    int*   sLV  = smem_i + 18496;
    int*   sScal = smem_i + 18560;

    int tid = threadIdx.x;
    int v0 = blockIdx.x * TVOX;
    int tx = tid & 15;
    int ty = tid >> 4;

    for (int i = tid; i < 704; i += 256) sW1[i] = W1[i];
    for (int i = tid; i < 4096; i += 256) sWX[i] = W2[i];          // rows 0..63
    for (int i = tid; i < 4096; i += 256) { sV1[i] = 0; sM[i] = INT_MIN; }

    // per-voxel stats (once per tile)
    if (tid < TVOX) {
        int v = v0 + tid;
        float mx = 0.f, my = 0.f, mz = 0.f, cenx = 0.f, ceny = 0.f;
        if (v < CANVAS) {
            float inv = 1.0f / fmaxf((float)g_cnt[v], 1.0f);
            mx = g_vsum[3 * v + 0] * inv;
            my = g_vsum[3 * v + 1] * inv;
            mz = g_vsum[3 * v + 2] * inv;
            int cxv = v % NXY;
            int cyv = v / NXY;
            cenx = (float)cxv * VXY + (VXY * 0.5f + PCMINX);
            ceny = (float)cyv * VXY + (VXY * 0.5f + PCMINY);
        }
        float* d = sVox + tid * 6;
        d[0] = mx; d[1] = my; d[2] = mz; d[3] = cenx; d[4] = ceny;
    }
    if (tid == 0) {
        sScal[0] = g_off[v0];
        sScal[1] = g_off[min(v0 + TVOX, CANVAS)];
    }
    __syncthreads();
    int p_start = sScal[0], p_end = sScal[1];

    // ---- point loop: 64-point chunks of this tile's sorted points
    for (int c0 = p_start; c0 < p_end; c0 += 64) {
        __syncthreads();   // previous chunk's GEMM/atomics done before overwrite
        int n_valid = min(64, p_end - c0);

        // phase 0: one thread per point slot builds features
        if (tid < 64) {
            int pos = c0 + tid;
            int lv = -1;
            float* f = sF + tid * 12;
            if (pos < p_end) {
                int pi = g_sorted[pos];
                lv = g_sflat[pos] - v0;
                float x  = pts[pi * 5 + 0];
                float y  = pts[pi * 5 + 1];
                float z  = pts[pi * 5 + 2];
                float p3 = pts[pi * 5 + 3];
                float p4 = pts[pi * 5 + 4];
                const float* vx = sVox + lv * 6;
                f[0] = x;  f[1] = y;  f[2] = z;  f[3] = p3;  f[4] = p4;
                f[5] = x - vx[0];  f[6] = y - vx[1];  f[7] = z - vx[2];
                f[8] = x - vx[3];  f[9] = y - vx[4];
                f[10] = z - (VZf * 0.5f + PCMINZ);
            }
            sLV[tid] = lv;
        }
        __syncthreads();

        // phase 1: pf1 channels; thread = (pt, cg). Padded slots skip all work.
        {
            int pt = tid >> 2;
            if (pt < n_valid) {
                int cg = tid & 3;
                int lv = sLV[pt];

                float f[11];
                #pragma unroll
                for (int k = 0; k < 11; k++) f[k] = sF[pt * 12 + k];

                const float4* w4 = (const float4*)sW1;   // [11][16] float4
                #pragma unroll
                for (int c4 = 0; c4 < 4; c4++) {
                    int ch = cg * 16 + c4 * 4;
                    float a0 = 0.f, a1 = 0.f, a2 = 0.f, a3 = 0.f;
                    #pragma unroll
                    for (int k = 0; k < 11; k++) {
                        float4 w = w4[k * 16 + (ch >> 2)];
                        a0 = fmaf(f[k], w.x, a0);
                        a1 = fmaf(f[k], w.y, a1);
                        a2 = fmaf(f[k], w.z, a2);
                        a3 = fmaf(f[k], w.w, a3);
                    }
                    a0 = fmaxf(a0, 0.f); a1 = fmaxf(a1, 0.f);
                    a2 = fmaxf(a2, 0.f); a3 = fmaxf(a3, 0.f);

                    float* d = sA + pt * SA_LD + ch;
                    d[0] = a0; d[1] = a1; d[2] = a2; d[3] = a3;

                    // smem segment max (relu>=0, init 0 -> exact)
                    int* vb = &sV1[lv * 64 + ch];
                    if (a0 > 0.f) atomicMax(vb + 0, __float_as_int(a0));
                    if (a1 > 0.f) atomicMax(vb + 1, __float_as_int(a1));
                    if (a2 > 0.f) atomicMax(vb + 2, __float_as_int(a2));
                    if (a3 > 0.f) atomicMax(vb + 3, __float_as_int(a3));
                }
            }
        }
        __syncthreads();

        // phase 2: GEMM s = sA @ W2a (4x4 micro-tile, K=64).
        // Row groups fully inside padding skip GEMM + epilogue entirely.
        if (ty * 4 < n_valid) {
            float acc[4][4];
            #pragma unroll
            for (int r = 0; r < 4; r++)
                #pragma unroll
                for (int c = 0; c < 4; c++) acc[r][c] = 0.f;

            #pragma unroll 16
            for (int k = 0; k < 64; k++) {
                float4 b = *(const float4*)&sWX[k * 64 + tx * 4];
                float a0 = sA[(ty * 4 + 0) * SA_LD + k];
                float a1 = sA[(ty * 4 + 1) * SA_LD + k];
                float a2 = sA[(ty * 4 + 2) * SA_LD + k];
                float a3 = sA[(ty * 4 + 3) * SA_LD + k];
                acc[0][0] = fmaf(a0, b.x, acc[0][0]); acc[0][1] = fmaf(a0, b.y, acc[0][1]);
                acc[0][2] = fmaf(a0, b.z, acc[0][2]); acc[0][3] = fmaf(a0, b.w, acc[0][3]);
                acc[1][0] = fmaf(a1, b.x, acc[1][0]); acc[1][1] = fmaf(a1, b.y, acc[1][1]);
                acc[1][2] = fmaf(a1, b.z, acc[1][2]); acc[1][3] = fmaf(a1, b.w, acc[1][3]);
                acc[2][0] = fmaf(a2, b.x, acc[2][0]); acc[2][1] = fmaf(a2, b.y, acc[2][1]);
                acc[2][2] = fmaf(a2, b.z, acc[2][2]); acc[2][3] = fmaf(a2, b.w, acc[2][3]);
                acc[3][0] = fmaf(a3, b.x, acc[3][0]); acc[3][1] = fmaf(a3, b.y, acc[3][1]);
                acc[3][2] = fmaf(a3, b.z, acc[3][2]); acc[3][3] = fmaf(a3, b.w, acc[3][3]);
            }

            // pre-relu segment max into sM (mapped, smem).
            // Rows beyond n_valid in a straddling group have lv = -1 -> skipped
            // (their acc may contain stale-sA garbage; it is never used).
            #pragma unroll
            for (int r = 0; r < 4; r++) {
                int lv = sLV[ty * 4 + r];
                if (lv >= 0) {
                    int* o = &sM[lv * 64 + tx * 4];
                    #pragma unroll
                    for (int c = 0; c < 4; c++)
                        atomicMax(o + c, fmap_bits(acc[r][c]));
                }
            }
        }
    }
    __syncthreads();

    // ---- final voxel GEMM: B = W2 rows 64..127
    for (int i = tid; i < 4096; i += 256) sWX[i] = W2[4096 + i];
    __syncthreads();

    float acc[4][4];
    #pragma unroll
    for (int r = 0; r < 4; r++)
        #pragma unroll
        for (int c = 0; c < 4; c++) acc[r][c] = 0.f;

    #pragma unroll 16
    for (int k = 0; k < 64; k++) {
        float4 b = *(const float4*)&sWX[k * 64 + tx * 4];
        float a0 = __int_as_float(sV1[(ty * 4 + 0) * 64 + k]);
        float a1 = __int_as_float(sV1[(ty * 4 + 1) * 64 + k]);
        float a2 = __int_as_float(sV1[(ty * 4 + 2) * 64 + k]);
        float a3 = __int_as_float(sV1[(ty * 4 + 3) * 64 + k]);
        acc[0][0] = fmaf(a0, b.x, acc[0][0]); acc[0][1] = fmaf(a0, b.y, acc[0][1]);
        acc[0][2] = fmaf(a0, b.z, acc[0][2]); acc[0][3] = fmaf(a0, b.w, acc[0][3]);
        acc[1][0] = fmaf(a1, b.x, acc[1][0]); acc[1][1] = fmaf(a1, b.y, acc[1][1]);
        acc[1][2] = fmaf(a1, b.z, acc[1][2]); acc[1][3] = fmaf(a1, b.w, acc[1][3]);
        acc[2][0] = fmaf(a2, b.x, acc[2][0]); acc[2][1] = fmaf(a2, b.y, acc[2][1]);
        acc[2][2] = fmaf(a2, b.z, acc[2][2]); acc[2][3] = fmaf(a2, b.w, acc[2][3]);
        acc[3][0] = fmaf(a3, b.x, acc[3][0]); acc[3][1] = fmaf(a3, b.y, acc[3][1]);
        acc[3][2] = fmaf(a3, b.z, acc[3][2]); acc[3][3] = fmaf(a3, b.w, acc[3][3]);
    }

    // dense epilogue: out = relu(acc + unmap(sM))
    #pragma unroll
    for (int r = 0; r < 4; r++) {
        int v = v0 + ty * 4 + r;
        if (v >= CANVAS) continue;
        const int* mrow = &sM[(ty * 4 + r) * 64 + tx * 4];
        float4 o;
        o.x = fmaxf(acc[r][0] + funmap_bits(mrow[0]), 0.f);
        o.y = fmaxf(acc[r][1] + funmap_bits(mrow[1]), 0.f);
        o.z = fmaxf(acc[r][2] + funmap_bits(mrow[2]), 0.f);
        o.w = fmaxf(acc[r][3] + funmap_bits(mrow[3]), 0.f);
        *(float4*)(out + (size_t)v * 64 + tx * 4) = o;
    }
}

// ---------------------------------------------------------------------------
extern "C" void kernel_launch(void* const* d_in, const int* in_sizes, int n_in,
                              void* d_out, int out_size) {
    const float* points = (const float*)d_in[0];  // [400000, 5]
    const float* W1     = (const float*)d_in[1];  // [11, 64]
    const float* W2     = (const float*)d_in[2];  // [128, 64]
    float* out = (float*)d_out;                   // [219024, 64]

    cudaFuncSetAttribute(k_main, cudaFuncAttributeMaxDynamicSharedMemorySize,
                         SMEM_MAIN_BYTES);

    k_zero<<<1024, 256>>>();
    k_scatter<<<(N_PTS + 255) / 256, 256>>>(points);
    k_scan1<<<NB, 256>>>();
    k_scan2<<<1, 1024>>>();
    k_scan3<<<NB, 256>>>();
    k_fill<<<(N_PTS + 255) / 256, 256>>>();
    k_main<<<NVT, 256, SMEM_MAIN_BYTES>>>(points, W1, W2, out);
}